// round 5
// baseline (speedup 1.0000x reference)
#include <cuda_runtime.h>
#include <math.h>

#define NP 512
#define TT 12

// ---------------- persistent state (device globals; re-initialized every launch) ----
__device__ float g_h[NP*64];
__device__ float g_c[NP*64];
__device__ float g_ctx[NP*64];
__device__ float g_pos[NP*2];
__device__ float g_cur[NP*2];
__device__ float g_A[NP*64];
__device__ float g_B[NP*64];
__device__ float g_M[2*64];
__device__ float g_bc[64];
__device__ float g_xc[NP*128];   // precomputed b_in + [c,z] @ W_in[2:98]

__device__ __forceinline__ float sigmf(float x){ return 1.0f/(1.0f + expf(-x)); }

// ---------------- init: copy initial state, zero ctx, fold W_sp/b_sp/b1 into M/bc ----
__global__ void k_init(const float* __restrict__ last_pos, const float* __restrict__ obs,
                       const float* __restrict__ h0, const float* __restrict__ c0,
                       const float* __restrict__ W_sp, const float* __restrict__ b_sp,
                       const float* __restrict__ W1, const float* __restrict__ b1)
{
    int idx = blockIdx.x*blockDim.x + threadIdx.x;
    if (idx < NP*64){ g_h[idx]=h0[idx]; g_c[idx]=c0[idx]; g_ctx[idx]=0.f; }
    if (idx < NP*2){ g_pos[idx]=last_pos[idx]; g_cur[idx]=obs[7*NP*2+idx]; }
    if (idx < 128){
        int f = idx>>6, m = idx&63; float s = 0.f;
        #pragma unroll 8
        for (int e=0;e<32;e++) s += W_sp[f*32+e]*W1[e*64+m];
        g_M[idx]=s;
    }
    if (idx < 64){
        float s = b1[idx];
        #pragma unroll 8
        for (int e=0;e<32;e++) s += b_sp[e]*W1[e*64+idx];
        g_bc[idx]=s;
    }
}

// ---------------- x_const precompute: 128 blocks x 128 threads, 4 agents/block ------
__global__ __launch_bounds__(128)
void k_xc(const float* __restrict__ c_in, const float* __restrict__ z,
          const float* __restrict__ W_in, const float* __restrict__ b_in)
{
    __shared__ float sh[4][96];
    const int tid = threadIdx.x;
    const int abase = blockIdx.x*4;
    #pragma unroll
    for (int r=0;r<3;r++){
        int idx = r*128+tid; int a = idx/96, e = idx%96;
        sh[a][e] = (e < 64) ? c_in[(abase+a)*64 + e] : z[(abase+a)*32 + e-64];
    }
    __syncthreads();
    float s0=b_in[tid], s1=s0, s2=s0, s3=s0;
    #pragma unroll 8
    for (int e=0;e<96;e++){
        float w = W_in[(2+e)*128 + tid];
        s0 = fmaf(sh[0][e], w, s0);
        s1 = fmaf(sh[1][e], w, s1);
        s2 = fmaf(sh[2][e], w, s2);
        s3 = fmaf(sh[3][e], w, s3);
    }
    g_xc[(abase+0)*128+tid]=s0;
    g_xc[(abase+1)*128+tid]=s1;
    g_xc[(abase+2)*128+tid]=s2;
    g_xc[(abase+3)*128+tid]=s3;
}

// ---------------- per-agent kernel: post(t-1) + embed + LSTM(t) + A/B(t) -----------
// 4 agents per block, 256 threads, 128 blocks. t in [0,12]; t==12 does only post(11).
__global__ __launch_bounds__(256)
void k_agent(int t,
             const float* __restrict__ eps,
             const float* __restrict__ W_in,
             const float* __restrict__ W_ih, const float* __restrict__ W_hh,
             const float* __restrict__ b_ih, const float* __restrict__ b_hh,
             const float* __restrict__ W_l2p, const float* __restrict__ b_l2p,
             const float* __restrict__ W1,
             float* __restrict__ out)
{
    __shared__ float sh_hold[4][64];
    __shared__ float sh_ctx[4][64];
    __shared__ float sh_pos[4][2];
    __shared__ float sh_x[4][128];
    __shared__ float sh_hnew[4][64];
    __shared__ float buf[256*33];   // reused: post scratch / W chunks / gates

    const int tid = threadIdx.x;
    const int abase = blockIdx.x*4;

    // load previous h and ctx
    {
        int a = tid>>6, d = tid&63;
        int gi = (abase+a)*64+d;
        sh_hold[a][d] = g_h[gi];
        sh_ctx [a][d] = g_ctx[gi];
    }
    __syncthreads();

    if (t > 0){
        int tp = t-1;
        if (tid < 16){
            int a = tid>>2, o = tid&3;    // o: 0=mu0 1=mu1 2=lv0 3=lv1
            int f = o & 1; int lv = o>>1;
            const float* hh = &sh_hold[a][lv?32:0];
            float s = b_l2p[f];
            #pragma unroll 8
            for (int d=0; d<32; d++) s = fmaf(hh[d], W_l2p[d*2+f], s);
            #pragma unroll 8
            for (int k=0; k<64; k++) s = fmaf(sh_ctx[a][k], W_l2p[(32+k)*2+f], s);
            int i = abase+a;
            out[(lv?2:1)*(TT*NP*2) + tp*NP*2 + i*2 + f] = s;   // mean / var(logvar)
            buf[a*4+o] = s;
        }
        __syncthreads();
        if (tid < 8){
            int a = tid>>1, f = tid&1; int i = abase+a;
            float mu = buf[a*4+f], lvv = buf[a*4+2+f];
            float p = mu + eps[tp*NP*2 + i*2 + f]*expf(0.5f*lvv);
            out[tp*NP*2 + i*2 + f] = p;                        // pre_pos
            sh_pos[a][f] = p;
            g_pos[i*2+f] = p;
            g_cur[i*2+f] += p;
        }
        __syncthreads();
    } else {
        if (tid < 8){ int a = tid>>1, f = tid&1; sh_pos[a][f] = g_pos[(abase+a)*2+f]; }
        __syncthreads();
    }
    if (t == TT) return;

    // ---- x = relu(x_const + pos@W_in[0:2] + ctx@W_in[98:162]) ----
    {
        int u = tid & 127; int a0 = tid >> 7;       // agents a0, a0+2
        float s0 = g_xc[(abase+a0  )*128+u];
        float s1 = g_xc[(abase+a0+2)*128+u];
        float w0 = W_in[u], w1 = W_in[128+u];
        s0 = fmaf(sh_pos[a0  ][0], w0, fmaf(sh_pos[a0  ][1], w1, s0));
        s1 = fmaf(sh_pos[a0+2][0], w0, fmaf(sh_pos[a0+2][1], w1, s1));
        #pragma unroll 8
        for (int k=0;k<64;k++){
            float w = W_in[(98+k)*128+u];
            s0 = fmaf(sh_ctx[a0  ][k], w, s0);
            s1 = fmaf(sh_ctx[a0+2][k], w, s1);
        }
        sh_x[a0  ][u] = fmaxf(s0,0.f);
        sh_x[a0+2][u] = fmaxf(s1,0.f);
    }
    __syncthreads();

    // ---- gates = x@W_ih^T + h@W_hh^T + b ; thread owns gate unit u4 = tid ----
    float acc[4];
    {
        float binit = b_ih[tid] + b_hh[tid];
        #pragma unroll
        for (int a=0;a<4;a++) acc[a]=binit;
    }
    #pragma unroll
    for (int vc=0; vc<4; vc++){
        #pragma unroll 8
        for (int r=0;r<32;r++){
            int idx = r*256+tid; int u4 = idx>>5, vv = idx&31;
            buf[u4*33+vv] = W_ih[u4*128 + vc*32 + vv];
        }
        __syncthreads();
        #pragma unroll
        for (int vv=0; vv<32; vv++){
            float wv = buf[tid*33+vv];
            #pragma unroll
            for (int a=0;a<4;a++) acc[a] = fmaf(sh_x[a][vc*32+vv], wv, acc[a]);
        }
        __syncthreads();
    }
    #pragma unroll
    for (int vc=0; vc<2; vc++){
        #pragma unroll 8
        for (int r=0;r<32;r++){
            int idx = r*256+tid; int u4 = idx>>5, vv = idx&31;
            buf[u4*33+vv] = W_hh[u4*64 + vc*32 + vv];
        }
        __syncthreads();
        #pragma unroll
        for (int vv=0; vv<32; vv++){
            float wv = buf[tid*33+vv];
            #pragma unroll
            for (int a=0;a<4;a++) acc[a] = fmaf(sh_hold[a][vc*32+vv], wv, acc[a]);
        }
        __syncthreads();
    }
    #pragma unroll
    for (int a=0;a<4;a++) buf[a*256+tid] = acc[a];
    __syncthreads();

    // ---- LSTM elementwise (256 threads = 4 agents x 64 dims) ----
    {
        int a = tid>>6, d = tid&63; int i = abase+a;
        float ig = buf[a*256      +d];
        float fg = buf[a*256 +  64+d];
        float gg = buf[a*256 + 128+d];
        float og = buf[a*256 + 192+d];
        float co = g_c[i*64+d];
        float cn = sigmf(fg)*co + sigmf(ig)*tanhf(gg);
        float hn = sigmf(og)*tanhf(cn);
        g_c[i*64+d] = cn;
        g_h[i*64+d] = hn;
        sh_hnew[a][d] = hn;
    }
    __syncthreads();

    // ---- A[j]=h@W1[32:96], B[i]=h@W1[96:160]+bc ----
    {
        int m = tid & 63; int w = (tid>>6)&1; int ah = tid>>7;  // agents ah, ah+2
        float s0 = w ? g_bc[m] : 0.f; float s1 = s0;
        const float* Wp = W1 + (32 + w*64)*64 + m;
        #pragma unroll 8
        for (int d=0; d<64; d++){
            float wv = Wp[d*64];
            s0 = fmaf(sh_hnew[ah  ][d], wv, s0);
            s1 = fmaf(sh_hnew[ah+2][d], wv, s1);
        }
        float* dst = w ? g_B : g_A;
        dst[(abase+ah  )*64+m] = s0;
        dst[(abase+ah+2)*64+m] = s1;
    }
}

// ---------------- pooling kernel: 512 blocks (1 row i), 256 threads, 128-pair tiles -
__global__ __launch_bounds__(256)
void k_pool(int t, const int* __restrict__ nei,
            const float* __restrict__ W2, const float* __restrict__ b2)
{
    __shared__ float sh_h1[64*132];    // [m][p], stride 132; reduction aliased here
    __shared__ float sh_W2[64*64];     // [m][k]
    __shared__ float sh_curj[256];     // 128 j * 2
    __shared__ int   sh_jidx[NP];
    __shared__ int   sh_cnt;

    const int tid = threadIdx.x;
    const int i = blockIdx.x;

    if (tid == 0) sh_cnt = 0;
    // W2 staging: float4
    {
        const float4* src = (const float4*)W2;
        float4* dst = (float4*)sh_W2;
        #pragma unroll
        for (int r=0;r<4;r++) dst[r*256+tid] = src[r*256+tid];
    }
    __syncthreads();

    // ---- compact valid neighbor indices (max is commutative; order irrelevant) ----
    {
        const int* row = nei + (long)t*NP*NP + (long)i*NP;
        #pragma unroll
        for (int c=0;c<2;c++){
            int j = c*256 + tid;
            int v = row[j] > 0;
            unsigned bal = __ballot_sync(0xFFFFFFFFu, v);
            int lane = tid & 31;
            int base = 0;
            if (lane == 0) base = atomicAdd(&sh_cnt, __popc(bal));
            base = __shfl_sync(0xFFFFFFFFu, base, 0);
            if (v) sh_jidx[base + __popc(bal & ((1u<<lane)-1u))] = j;
        }
    }
    __syncthreads();
    const int cnt = sh_cnt;
    const int ntiles = (cnt + 127) >> 7;

    const int mm = tid & 63, q = tid >> 6;      // stage-1 mapping
    const float M0 = g_M[mm], M1 = g_M[64+mm];
    const float Bi = g_B[i*64+mm];
    const float cix = g_cur[i*2], ciy = g_cur[i*2+1];

    const int kq = tid & 15, jg = tid >> 4;     // 16 j-groups of 8, 16 k-quads
    float b2r[4];
    #pragma unroll
    for (int kk=0;kk<4;kk++) b2r[kk] = b2[kq*4+kk];
    float cacc[4] = {0.f,0.f,0.f,0.f};

    for (int jt=0; jt<ntiles; jt++){
        __syncthreads();                         // protect sh_h1/sh_curj reuse
        {
            int p = tid>>1, f = tid&1;
            int gp = jt*128 + p;
            int j = sh_jidx[(gp < cnt) ? gp : 0];
            sh_curj[p*2+f] = g_cur[j*2+f];
        }
        __syncthreads();

        // stage 1: h1 for 128 compacted pairs x 64 m
        #pragma unroll 4
        for (int r=0;r<32;r++){
            int p = r*4 + q;
            int gp = jt*128 + p;
            int j = sh_jidx[(gp < cnt) ? gp : 0];
            float dx = cix - sh_curj[p*2];
            float dy = ciy - sh_curj[p*2+1];
            float v  = g_A[j*64 + mm] + Bi;
            v = fmaf(dx, M0, fmaf(dy, M1, v));
            sh_h1[mm*132 + p] = fmaxf(v, 0.f);
        }
        __syncthreads();

        // stage 2: h2 = h1 @ W2 (8 jj x 4 k per thread), masked max epilogue
        float acc[8][4];
        #pragma unroll
        for (int jj=0;jj<8;jj++){
            #pragma unroll
            for (int kk=0;kk<4;kk++) acc[jj][kk]=0.f;
        }
        #pragma unroll 16
        for (int m=0;m<64;m++){
            const float4 w = *(const float4*)(sh_W2 + m*64 + kq*4);
            const float* hp = sh_h1 + m*132 + (jg<<3);
            float4 ha = *(const float4*)(hp);
            float4 hb = *(const float4*)(hp+4);
            float hv[8] = {ha.x,ha.y,ha.z,ha.w,hb.x,hb.y,hb.z,hb.w};
            #pragma unroll
            for (int jj=0;jj<8;jj++){
                acc[jj][0] = fmaf(hv[jj], w.x, acc[jj][0]);
                acc[jj][1] = fmaf(hv[jj], w.y, acc[jj][1]);
                acc[jj][2] = fmaf(hv[jj], w.z, acc[jj][2]);
                acc[jj][3] = fmaf(hv[jj], w.w, acc[jj][3]);
            }
        }
        #pragma unroll
        for (int jj=0;jj<8;jj++){
            int gp = jt*128 + jg*8 + jj;
            if (gp < cnt){
                #pragma unroll
                for (int kk=0;kk<4;kk++)
                    cacc[kk] = fmaxf(cacc[kk], acc[jj][kk] + b2r[kk]);
            }
        }
    }

    // final reduction over 16 jg groups; alias reduction buffer onto sh_h1
    __syncthreads();
    float* sh_red = sh_h1;             // 16*64 floats, all stage-2 reads are done
    #pragma unroll
    for (int kk=0;kk<4;kk++) sh_red[jg*64 + kq*4+kk] = cacc[kk];
    __syncthreads();
    if (tid < 64){
        float v = sh_red[tid];
        #pragma unroll
        for (int g=1; g<16; g++) v = fmaxf(v, sh_red[g*64 + tid]);
        g_ctx[i*64 + tid] = v;
    }
}

// ---------------- launch ------------------------------------------------------------
extern "C" void kernel_launch(void* const* d_in, const int* in_sizes, int n_in,
                              void* d_out, int out_size)
{
    const float* last_pos = (const float*)d_in[0];
    const float* c_in     = (const float*)d_in[1];
    const float* z        = (const float*)d_in[2];
    const float* obs      = (const float*)d_in[3];
    const int*   nei      = (const int*)  d_in[4];
    // d_in[5] nei_num_index: unused by reference
    const float* h0       = (const float*)d_in[6];
    const float* c0       = (const float*)d_in[7];
    const float* eps      = (const float*)d_in[8];
    const float* W_in     = (const float*)d_in[9];
    const float* b_in     = (const float*)d_in[10];
    const float* W_ih     = (const float*)d_in[11];
    const float* W_hh     = (const float*)d_in[12];
    const float* b_ih     = (const float*)d_in[13];
    const float* b_hh     = (const float*)d_in[14];
    const float* W_l2p    = (const float*)d_in[15];
    const float* b_l2p    = (const float*)d_in[16];
    const float* W_sp     = (const float*)d_in[17];
    const float* b_sp     = (const float*)d_in[18];
    const float* W1       = (const float*)d_in[19];
    const float* b1       = (const float*)d_in[20];
    const float* W2       = (const float*)d_in[21];
    const float* b2       = (const float*)d_in[22];
    float* out = (float*)d_out;

    k_init<<<128, 256>>>(last_pos, obs, h0, c0, W_sp, b_sp, W1, b1);
    k_xc<<<128, 128>>>(c_in, z, W_in, b_in);

    for (int t=0; t<TT; t++){
        k_agent<<<128, 256>>>(t, eps, W_in, W_ih, W_hh,
                              b_ih, b_hh, W_l2p, b_l2p, W1, out);
        k_pool<<<512, 256>>>(t, nei, W2, b2);
    }
    // final post (outputs for t = 11)
    k_agent<<<128, 256>>>(TT, eps, W_in, W_ih, W_hh,
                          b_ih, b_hh, W_l2p, b_l2p, W1, out);
}

// round 7
// speedup vs baseline: 1.3012x; 1.3012x over previous
#include <cuda_runtime.h>
#include <math.h>

#define NP 512
#define TT 12

typedef unsigned long long ull;

// ---------------- f32x2 packed helpers (sm_103a) ------------------------------------
__device__ __forceinline__ ull f32x2_fma(ull a, ull b, ull c){
    ull d;
    asm("fma.rn.f32x2 %0, %1, %2, %3;" : "=l"(d) : "l"(a), "l"(b), "l"(c));
    return d;
}
__device__ __forceinline__ ull f32x2_dup(float x){
    ull d;
    asm("mov.b64 %0, {%1, %1};" : "=l"(d) : "f"(x));
    return d;
}
#define UNPACK2(lo, hi, v) asm("mov.b64 {%0, %1}, %2;" : "=f"(lo), "=f"(hi) : "l"(v))

// ---------------- persistent state (device globals; re-initialized every launch) ----
__device__ float g_h[NP*64];
__device__ float g_c[NP*64];
__device__ float g_ctx[NP*64];
__device__ float g_pos[NP*2];
__device__ float g_cur[NP*2];
__device__ float g_A[NP*64];     // A'[j] = h_j@W1_hj - cur_j . M   (spatial term folded)
__device__ float g_B[NP*64];     // B'[i] = h_i@W1_hi + bc + cur_i . M
__device__ float g_M[2*64];
__device__ float g_bc[64];
__device__ float g_xc[NP*128];   // precomputed b_in + [c,z] @ W_in[2:98]
__device__ float g_WihT[128*256];// W_ih transposed: [v][u]
__device__ float g_WhhT[64*256]; // W_hh transposed: [v][u]

__device__ __forceinline__ float sigmf(float x){ return 1.0f/(1.0f + expf(-x)); }

// ---------------- init: copy state, fold W_sp/b_sp/b1 into M/bc, transpose LSTM W ---
__global__ void k_init(const float* __restrict__ last_pos, const float* __restrict__ obs,
                       const float* __restrict__ h0, const float* __restrict__ c0,
                       const float* __restrict__ W_sp, const float* __restrict__ b_sp,
                       const float* __restrict__ W1, const float* __restrict__ b1,
                       const float* __restrict__ W_ih, const float* __restrict__ W_hh)
{
    int idx = blockIdx.x*blockDim.x + threadIdx.x;
    if (idx < NP*64){ g_h[idx]=h0[idx]; g_c[idx]=c0[idx]; g_ctx[idx]=0.f; }
    if (idx < NP*2){ g_pos[idx]=last_pos[idx]; g_cur[idx]=obs[7*NP*2+idx]; }
    if (idx < 128){
        int f = idx>>6, m = idx&63; float s = 0.f;
        #pragma unroll 8
        for (int e=0;e<32;e++) s += W_sp[f*32+e]*W1[e*64+m];
        g_M[idx]=s;
    }
    if (idx < 64){
        float s = b1[idx];
        #pragma unroll 8
        for (int e=0;e<32;e++) s += b_sp[e]*W1[e*64+idx];
        g_bc[idx]=s;
    }
    // transposes (coalesced reads)
    if (idx < 256*128){
        int u = idx>>7, v = idx&127;
        g_WihT[v*256+u] = W_ih[idx];
    }
    if (idx < 256*64){
        int u = idx>>6, v = idx&63;
        g_WhhT[v*256+u] = W_hh[idx];
    }
}

// ---------------- x_const precompute: 128 blocks x 128 threads, 4 agents/block ------
__global__ __launch_bounds__(128)
void k_xc(const float* __restrict__ c_in, const float* __restrict__ z,
          const float* __restrict__ W_in, const float* __restrict__ b_in)
{
    __shared__ float sh[4][96];
    const int tid = threadIdx.x;
    const int abase = blockIdx.x*4;
    #pragma unroll
    for (int r=0;r<3;r++){
        int idx = r*128+tid; int a = idx/96, e = idx%96;
        sh[a][e] = (e < 64) ? c_in[(abase+a)*64 + e] : z[(abase+a)*32 + e-64];
    }
    __syncthreads();
    float s0=b_in[tid], s1=s0, s2=s0, s3=s0;
    #pragma unroll 8
    for (int e=0;e<96;e++){
        float w = W_in[(2+e)*128 + tid];
        s0 = fmaf(sh[0][e], w, s0);
        s1 = fmaf(sh[1][e], w, s1);
        s2 = fmaf(sh[2][e], w, s2);
        s3 = fmaf(sh[3][e], w, s3);
    }
    g_xc[(abase+0)*128+tid]=s0;
    g_xc[(abase+1)*128+tid]=s1;
    g_xc[(abase+2)*128+tid]=s2;
    g_xc[(abase+3)*128+tid]=s3;
}

// ---------------- per-agent kernel: post(t-1) + embed + LSTM(t) + A'/B'(t) ---------
// 4 agents per block, 256 threads, 128 blocks. t in [0,12]; t==12 does only post(11).
__global__ __launch_bounds__(256)
void k_agent(int t,
             const float* __restrict__ eps,
             const float* __restrict__ W_in,
             const float* __restrict__ b_ih, const float* __restrict__ b_hh,
             const float* __restrict__ W_l2p, const float* __restrict__ b_l2p,
             const float* __restrict__ W1,
             float* __restrict__ out)
{
    __shared__ float sh_hold[4][64];
    __shared__ __align__(16) float sh_hT[64*4];    // h transposed [d][a]
    __shared__ float sh_ctx[4][64];
    __shared__ float sh_pos[4][2];
    __shared__ __align__(16) float sh_xT[128*4];   // x transposed [u][a]
    __shared__ float sh_hnew[4][64];
    __shared__ float buf[1024];

    const int tid = threadIdx.x;
    const int abase = blockIdx.x*4;

    // load previous h and ctx; build transposed h
    {
        int a = tid>>6, d = tid&63;
        int gi = (abase+a)*64+d;
        float hv = g_h[gi];
        sh_hold[a][d] = hv;
        sh_hT[d*4+a]  = hv;
        sh_ctx [a][d] = g_ctx[gi];
    }
    __syncthreads();

    if (t > 0){
        int tp = t-1;
        if (tid < 16){
            int a = tid>>2, o = tid&3;    // o: 0=mu0 1=mu1 2=lv0 3=lv1
            int f = o & 1; int lv = o>>1;
            const float* hh = &sh_hold[a][lv?32:0];
            float s = b_l2p[f];
            #pragma unroll 8
            for (int d=0; d<32; d++) s = fmaf(hh[d], W_l2p[d*2+f], s);
            #pragma unroll 8
            for (int k=0; k<64; k++) s = fmaf(sh_ctx[a][k], W_l2p[(32+k)*2+f], s);
            int i = abase+a;
            out[(lv?2:1)*(TT*NP*2) + tp*NP*2 + i*2 + f] = s;   // mean / var(logvar)
            buf[a*4+o] = s;
        }
        __syncthreads();
        if (tid < 8){
            int a = tid>>1, f = tid&1; int i = abase+a;
            float mu = buf[a*4+f], lvv = buf[a*4+2+f];
            float p = mu + eps[tp*NP*2 + i*2 + f]*expf(0.5f*lvv);
            out[tp*NP*2 + i*2 + f] = p;                        // pre_pos
            sh_pos[a][f] = p;
            g_pos[i*2+f] = p;
            g_cur[i*2+f] += p;
        }
        __syncthreads();
    } else {
        if (tid < 8){ int a = tid>>1, f = tid&1; sh_pos[a][f] = g_pos[(abase+a)*2+f]; }
        __syncthreads();
    }
    if (t == TT) return;

    // ---- x = relu(x_const + pos@W_in[0:2] + ctx@W_in[98:162]); store transposed ----
    {
        int u = tid & 127; int a0 = tid >> 7;       // agents a0, a0+2
        float s0 = g_xc[(abase+a0  )*128+u];
        float s1 = g_xc[(abase+a0+2)*128+u];
        float w0 = W_in[u], w1 = W_in[128+u];
        s0 = fmaf(sh_pos[a0  ][0], w0, fmaf(sh_pos[a0  ][1], w1, s0));
        s1 = fmaf(sh_pos[a0+2][0], w0, fmaf(sh_pos[a0+2][1], w1, s1));
        #pragma unroll 8
        for (int k=0;k<64;k++){
            float w = W_in[(98+k)*128+u];
            s0 = fmaf(sh_ctx[a0  ][k], w, s0);
            s1 = fmaf(sh_ctx[a0+2][k], w, s1);
        }
        sh_xT[u*4 + a0    ] = fmaxf(s0,0.f);
        sh_xT[u*4 + a0 + 2] = fmaxf(s1,0.f);
    }
    __syncthreads();

    // ---- gates = x@W_ih^T + h@W_hh^T + b ; transposed global weights, f32x2 --------
    // buf layout: agent-major, buf[a*256 + u] where u = gate*64 + dim
    {
        float binit = b_ih[tid] + b_hh[tid];
        ull acc01 = f32x2_dup(binit);
        ull acc23 = acc01;
        #pragma unroll 8
        for (int v=0; v<128; v++){
            ull wd = f32x2_dup(g_WihT[v*256+tid]);
            ulonglong2 xv = *(const ulonglong2*)(sh_xT + v*4);
            acc01 = f32x2_fma(xv.x, wd, acc01);
            acc23 = f32x2_fma(xv.y, wd, acc23);
        }
        #pragma unroll 8
        for (int v=0; v<64; v++){
            ull wd = f32x2_dup(g_WhhT[v*256+tid]);
            ulonglong2 hv = *(const ulonglong2*)(sh_hT + v*4);
            acc01 = f32x2_fma(hv.x, wd, acc01);
            acc23 = f32x2_fma(hv.y, wd, acc23);
        }
        float a0,a1,a2,a3;
        UNPACK2(a0,a1,acc01);
        UNPACK2(a2,a3,acc23);
        buf[0*256+tid]=a0; buf[1*256+tid]=a1; buf[2*256+tid]=a2; buf[3*256+tid]=a3;
    }
    __syncthreads();

    // ---- LSTM elementwise (256 threads = 4 agents x 64 dims) ----
    // FIX (round 6 bug): read agent-major buf[a*256 + gate*64 + d]
    {
        int a = tid>>6, d = tid&63; int i = abase+a;
        float ig = buf[a*256 +   0 + d];
        float fg = buf[a*256 +  64 + d];
        float gg = buf[a*256 + 128 + d];
        float og = buf[a*256 + 192 + d];
        float co = g_c[i*64+d];
        float cn = sigmf(fg)*co + sigmf(ig)*tanhf(gg);
        float hn = sigmf(og)*tanhf(cn);
        g_c[i*64+d] = cn;
        g_h[i*64+d] = hn;
        sh_hnew[a][d] = hn;
    }
    __syncthreads();

    // ---- A'[j]=h@W1[32:96] - cur_j.M,  B'[i]=h@W1[96:160]+bc + cur_i.M -------------
    {
        int m = tid & 63; int w = (tid>>6)&1; int ah = tid>>7;  // agents ah, ah+2
        float s0 = w ? g_bc[m] : 0.f; float s1 = s0;
        const float* Wp = W1 + (32 + w*64)*64 + m;
        #pragma unroll 8
        for (int d=0; d<64; d++){
            float wv = Wp[d*64];
            s0 = fmaf(sh_hnew[ah  ][d], wv, s0);
            s1 = fmaf(sh_hnew[ah+2][d], wv, s1);
        }
        float m0 = g_M[m], m1 = g_M[64+m];
        float sg = w ? 1.f : -1.f;
        float cx0 = g_cur[(abase+ah  )*2], cy0 = g_cur[(abase+ah  )*2+1];
        float cx1 = g_cur[(abase+ah+2)*2], cy1 = g_cur[(abase+ah+2)*2+1];
        s0 = fmaf(sg*cx0, m0, fmaf(sg*cy0, m1, s0));
        s1 = fmaf(sg*cx1, m0, fmaf(sg*cy1, m1, s1));
        float* dst = w ? g_B : g_A;
        dst[(abase+ah  )*64+m] = s0;
        dst[(abase+ah+2)*64+m] = s1;
    }
}

// ---------------- pooling kernel: 512 blocks (1 row i), 256 threads, 128-pair tiles -
// stage 1: h1[m][p] = relu(A'[j_p][m] + B'[i][m]); stage 2: f32x2 GEMM + masked max.
__global__ __launch_bounds__(256)
void k_pool(int t, const int* __restrict__ nei,
            const float* __restrict__ W2, const float* __restrict__ b2)
{
    __shared__ __align__(16) float sh_h1[64*132];  // [m][p] stride 132; red aliased
    __shared__ __align__(16) float sh_W2[64*64];   // [m][k]
    __shared__ int   sh_jidx[NP];
    __shared__ int   sh_cnt;

    const int tid = threadIdx.x;
    const int i = blockIdx.x;

    if (tid == 0) sh_cnt = 0;
    {
        const float4* src = (const float4*)W2;
        float4* dst = (float4*)sh_W2;
        #pragma unroll
        for (int r=0;r<4;r++) dst[r*256+tid] = src[r*256+tid];
    }
    __syncthreads();

    // ---- compact valid neighbor indices (max is commutative; order irrelevant) ----
    {
        const int* row = nei + (long)t*NP*NP + (long)i*NP;
        #pragma unroll
        for (int c=0;c<2;c++){
            int j = c*256 + tid;
            int v = row[j] > 0;
            unsigned bal = __ballot_sync(0xFFFFFFFFu, v);
            int lane = tid & 31;
            int base = 0;
            if (lane == 0) base = atomicAdd(&sh_cnt, __popc(bal));
            base = __shfl_sync(0xFFFFFFFFu, base, 0);
            if (v) sh_jidx[base + __popc(bal & ((1u<<lane)-1u))] = j;
        }
    }
    __syncthreads();
    const int cnt = sh_cnt;
    const int ntiles = (cnt + 127) >> 7;

    const int mm = tid & 63, q = tid >> 6;      // stage-1 mapping
    const float Bi = g_B[i*64+mm];

    const int kq = tid & 15, jg = tid >> 4;     // 16 j-groups of 8, 16 k-quads
    float b2r[4];
    #pragma unroll
    for (int kk=0;kk<4;kk++) b2r[kk] = b2[kq*4+kk];
    float cacc[4] = {0.f,0.f,0.f,0.f};

    for (int jt=0; jt<ntiles; jt++){
        const int tile_cnt = min(128, cnt - jt*128);
        __syncthreads();                         // protect sh_h1 reuse

        // stage 1: h1 for 128 pairs x 64 m; batched loads for MLP
        #pragma unroll
        for (int rb=0; rb<4; rb++){
            float a8[8];
            #pragma unroll
            for (int r2=0; r2<8; r2++){
                int p = (rb*8+r2)*4 + q;
                int gp = jt*128 + p;
                int j = sh_jidx[(gp < cnt) ? gp : 0];
                a8[r2] = g_A[j*64 + mm];
            }
            #pragma unroll
            for (int r2=0; r2<8; r2++){
                int p = (rb*8+r2)*4 + q;
                sh_h1[mm*132 + p] = fmaxf(a8[r2] + Bi, 0.f);
            }
        }
        __syncthreads();

        // stage 2: packed f32x2 GEMM, 4 j-pairs x 4 k per thread; skip idle warps
        if (jg*8 < tile_cnt){
            ull acc2[4][4];
            #pragma unroll
            for (int jp=0;jp<4;jp++)
                #pragma unroll
                for (int kk=0;kk<4;kk++) acc2[jp][kk] = 0ull;

            #pragma unroll 8
            for (int m=0;m<64;m++){
                const float4 wv = *(const float4*)(sh_W2 + m*64 + kq*4);
                ull w0 = f32x2_dup(wv.x), w1 = f32x2_dup(wv.y);
                ull w2 = f32x2_dup(wv.z), w3 = f32x2_dup(wv.w);
                const ull* hp = (const ull*)(sh_h1 + m*132 + (jg<<3));
                ulonglong2 hA = *(const ulonglong2*)(hp);
                ulonglong2 hB = *(const ulonglong2*)(hp+2);
                acc2[0][0]=f32x2_fma(hA.x,w0,acc2[0][0]);
                acc2[0][1]=f32x2_fma(hA.x,w1,acc2[0][1]);
                acc2[0][2]=f32x2_fma(hA.x,w2,acc2[0][2]);
                acc2[0][3]=f32x2_fma(hA.x,w3,acc2[0][3]);
                acc2[1][0]=f32x2_fma(hA.y,w0,acc2[1][0]);
                acc2[1][1]=f32x2_fma(hA.y,w1,acc2[1][1]);
                acc2[1][2]=f32x2_fma(hA.y,w2,acc2[1][2]);
                acc2[1][3]=f32x2_fma(hA.y,w3,acc2[1][3]);
                acc2[2][0]=f32x2_fma(hB.x,w0,acc2[2][0]);
                acc2[2][1]=f32x2_fma(hB.x,w1,acc2[2][1]);
                acc2[2][2]=f32x2_fma(hB.x,w2,acc2[2][2]);
                acc2[2][3]=f32x2_fma(hB.x,w3,acc2[2][3]);
                acc2[3][0]=f32x2_fma(hB.y,w0,acc2[3][0]);
                acc2[3][1]=f32x2_fma(hB.y,w1,acc2[3][1]);
                acc2[3][2]=f32x2_fma(hB.y,w2,acc2[3][2]);
                acc2[3][3]=f32x2_fma(hB.y,w3,acc2[3][3]);
            }

            #pragma unroll
            for (int jp=0;jp<4;jp++){
                int gp0 = jt*128 + jg*8 + jp*2;
                #pragma unroll
                for (int kk=0;kk<4;kk++){
                    float lo, hi;
                    UNPACK2(lo, hi, acc2[jp][kk]);
                    if (gp0     < cnt) cacc[kk] = fmaxf(cacc[kk], lo + b2r[kk]);
                    if (gp0 + 1 < cnt) cacc[kk] = fmaxf(cacc[kk], hi + b2r[kk]);
                }
            }
        }
    }

    // final reduction over 16 jg groups; alias reduction buffer onto sh_h1
    __syncthreads();
    float* sh_red = sh_h1;
    #pragma unroll
    for (int kk=0;kk<4;kk++) sh_red[jg*64 + kq*4+kk] = cacc[kk];
    __syncthreads();
    if (tid < 64){
        float v = sh_red[tid];
        #pragma unroll
        for (int g=1; g<16; g++) v = fmaxf(v, sh_red[g*64 + tid]);
        g_ctx[i*64 + tid] = v;
    }
}

// ---------------- launch ------------------------------------------------------------
extern "C" void kernel_launch(void* const* d_in, const int* in_sizes, int n_in,
                              void* d_out, int out_size)
{
    const float* last_pos = (const float*)d_in[0];
    const float* c_in     = (const float*)d_in[1];
    const float* z        = (const float*)d_in[2];
    const float* obs      = (const float*)d_in[3];
    const int*   nei      = (const int*)  d_in[4];
    // d_in[5] nei_num_index: unused by reference
    const float* h0       = (const float*)d_in[6];
    const float* c0       = (const float*)d_in[7];
    const float* eps      = (const float*)d_in[8];
    const float* W_in     = (const float*)d_in[9];
    const float* b_in     = (const float*)d_in[10];
    const float* W_ih     = (const float*)d_in[11];
    const float* W_hh     = (const float*)d_in[12];
    const float* b_ih     = (const float*)d_in[13];
    const float* b_hh     = (const float*)d_in[14];
    const float* W_l2p    = (const float*)d_in[15];
    const float* b_l2p    = (const float*)d_in[16];
    const float* W_sp     = (const float*)d_in[17];
    const float* b_sp     = (const float*)d_in[18];
    const float* W1       = (const float*)d_in[19];
    const float* b1       = (const float*)d_in[20];
    const float* W2       = (const float*)d_in[21];
    const float* b2       = (const float*)d_in[22];
    float* out = (float*)d_out;

    k_init<<<128, 256>>>(last_pos, obs, h0, c0, W_sp, b_sp, W1, b1, W_ih, W_hh);
    k_xc<<<128, 128>>>(c_in, z, W_in, b_in);

    for (int t=0; t<TT; t++){
        k_agent<<<128, 256>>>(t, eps, W_in, b_ih, b_hh, W_l2p, b_l2p, W1, out);
        k_pool<<<512, 256>>>(t, nei, W2, b2);
    }
    // final post (outputs for t = 11)
    k_agent<<<128, 256>>>(TT, eps, W_in, b_ih, b_hh, W_l2p, b_l2p, W1, out);
}

// round 8
// speedup vs baseline: 1.6551x; 1.2720x over previous
#include <cuda_runtime.h>
#include <math.h>

#define NP 512
#define TT 12

typedef unsigned long long ull;

// ---------------- f32x2 packed helpers (sm_103a) ------------------------------------
__device__ __forceinline__ ull f32x2_fma(ull a, ull b, ull c){
    ull d;
    asm("fma.rn.f32x2 %0, %1, %2, %3;" : "=l"(d) : "l"(a), "l"(b), "l"(c));
    return d;
}
__device__ __forceinline__ ull f32x2_dup(float x){
    ull d;
    asm("mov.b64 %0, {%1, %1};" : "=l"(d) : "f"(x));
    return d;
}
#define UNPACK2(lo, hi, v) asm("mov.b64 {%0, %1}, %2;" : "=f"(lo), "=f"(hi) : "l"(v))

// ---------------- persistent state (device globals; re-initialized every launch) ----
__device__ float g_h[NP*64];
__device__ float g_c[NP*64];
__device__ float g_ctx[NP*64];
__device__ float g_pos[NP*2];
__device__ float g_cur[NP*2];
__device__ float g_A[NP*64];     // A'[j] = h_j@W1_hj - cur_j . M   (spatial term folded)
__device__ float g_B[NP*64];     // B'[i] = h_i@W1_hi + bc + cur_i . M
__device__ float g_M[2*64];
__device__ float g_bc[64];
__device__ float g_xc[NP*128];   // precomputed b_in + [c,z] @ W_in[2:98]
__device__ float g_WihT[128*256];// W_ih transposed: [v][u]
__device__ float g_WhhT[64*256]; // W_hh transposed: [v][u]

__device__ __forceinline__ float sigmf(float x){ return 1.0f/(1.0f + expf(-x)); }

// ---------------- init: copy state, fold W_sp/b_sp/b1 into M/bc, transpose LSTM W ---
__global__ void k_init(const float* __restrict__ last_pos, const float* __restrict__ obs,
                       const float* __restrict__ h0, const float* __restrict__ c0,
                       const float* __restrict__ W_sp, const float* __restrict__ b_sp,
                       const float* __restrict__ W1, const float* __restrict__ b1,
                       const float* __restrict__ W_ih, const float* __restrict__ W_hh)
{
    int idx = blockIdx.x*blockDim.x + threadIdx.x;
    if (idx < NP*64){ g_h[idx]=h0[idx]; g_c[idx]=c0[idx]; g_ctx[idx]=0.f; }
    if (idx < NP*2){ g_pos[idx]=last_pos[idx]; g_cur[idx]=obs[7*NP*2+idx]; }
    if (idx < 128){
        int f = idx>>6, m = idx&63; float s = 0.f;
        #pragma unroll 8
        for (int e=0;e<32;e++) s += W_sp[f*32+e]*W1[e*64+m];
        g_M[idx]=s;
    }
    if (idx < 64){
        float s = b1[idx];
        #pragma unroll 8
        for (int e=0;e<32;e++) s += b_sp[e]*W1[e*64+idx];
        g_bc[idx]=s;
    }
    // transposes (coalesced reads)
    if (idx < 256*128){
        int u = idx>>7, v = idx&127;
        g_WihT[v*256+u] = W_ih[idx];
    }
    if (idx < 256*64){
        int u = idx>>6, v = idx&63;
        g_WhhT[v*256+u] = W_hh[idx];
    }
}

// ---------------- x_const precompute: 128 blocks x 128 threads, 4 agents/block ------
__global__ __launch_bounds__(128)
void k_xc(const float* __restrict__ c_in, const float* __restrict__ z,
          const float* __restrict__ W_in, const float* __restrict__ b_in)
{
    __shared__ float sh[4][96];
    const int tid = threadIdx.x;
    const int abase = blockIdx.x*4;
    #pragma unroll
    for (int r=0;r<3;r++){
        int idx = r*128+tid; int a = idx/96, e = idx%96;
        sh[a][e] = (e < 64) ? c_in[(abase+a)*64 + e] : z[(abase+a)*32 + e-64];
    }
    __syncthreads();
    float s0=b_in[tid], s1=s0, s2=s0, s3=s0;
    #pragma unroll 8
    for (int e=0;e<96;e++){
        float w = W_in[(2+e)*128 + tid];
        s0 = fmaf(sh[0][e], w, s0);
        s1 = fmaf(sh[1][e], w, s1);
        s2 = fmaf(sh[2][e], w, s2);
        s3 = fmaf(sh[3][e], w, s3);
    }
    g_xc[(abase+0)*128+tid]=s0;
    g_xc[(abase+1)*128+tid]=s1;
    g_xc[(abase+2)*128+tid]=s2;
    g_xc[(abase+3)*128+tid]=s3;
}

// ---------------- per-agent kernel: post(t-1) + embed + LSTM(t) + A'/B'(t) ---------
// 4 agents per block, 256 threads, 128 blocks. t in [0,12]; t==12 does only post(11).
__global__ __launch_bounds__(256, 1)
void k_agent(int t,
             const float* __restrict__ eps,
             const float* __restrict__ W_in,
             const float* __restrict__ b_ih, const float* __restrict__ b_hh,
             const float* __restrict__ W_l2p, const float* __restrict__ b_l2p,
             const float* __restrict__ W1,
             float* __restrict__ out)
{
    __shared__ float sh_hold[4][64];
    __shared__ __align__(16) float sh_hT[64*4];    // h transposed [d][a]
    __shared__ float sh_ctx[4][64];
    __shared__ float sh_pos[4][2];
    __shared__ __align__(16) float sh_xT[128*4];   // x transposed [u][a]
    __shared__ float sh_hnew[4][64];
    __shared__ float buf[1024];

    const int tid = threadIdx.x;
    const int abase = blockIdx.x*4;

    // load previous h and ctx; build transposed h
    {
        int a = tid>>6, d = tid&63;
        int gi = (abase+a)*64+d;
        float hv = g_h[gi];
        sh_hold[a][d] = hv;
        sh_hT[d*4+a]  = hv;
        sh_ctx [a][d] = g_ctx[gi];
    }
    __syncthreads();

    if (t > 0){
        int tp = t-1;
        if (tid < 16){
            int a = tid>>2, o = tid&3;    // o: 0=mu0 1=mu1 2=lv0 3=lv1
            int f = o & 1; int lv = o>>1;
            const float* hh = &sh_hold[a][lv?32:0];
            float s = b_l2p[f];
            #pragma unroll 8
            for (int d=0; d<32; d++) s = fmaf(hh[d], W_l2p[d*2+f], s);
            #pragma unroll 8
            for (int k=0; k<64; k++) s = fmaf(sh_ctx[a][k], W_l2p[(32+k)*2+f], s);
            int i = abase+a;
            out[(lv?2:1)*(TT*NP*2) + tp*NP*2 + i*2 + f] = s;   // mean / var(logvar)
            buf[a*4+o] = s;
        }
        __syncthreads();
        if (tid < 8){
            int a = tid>>1, f = tid&1; int i = abase+a;
            float mu = buf[a*4+f], lvv = buf[a*4+2+f];
            float p = mu + eps[tp*NP*2 + i*2 + f]*expf(0.5f*lvv);
            out[tp*NP*2 + i*2 + f] = p;                        // pre_pos
            sh_pos[a][f] = p;
            g_pos[i*2+f] = p;
            g_cur[i*2+f] += p;
        }
        __syncthreads();
    } else {
        if (tid < 8){ int a = tid>>1, f = tid&1; sh_pos[a][f] = g_pos[(abase+a)*2+f]; }
        __syncthreads();
    }
    if (t == TT) return;

    // ---- x = relu(x_const + pos@W_in[0:2] + ctx@W_in[98:162]); store transposed ----
    {
        int u = tid & 127; int a0 = tid >> 7;       // agents a0, a0+2
        float s0 = g_xc[(abase+a0  )*128+u];
        float s1 = g_xc[(abase+a0+2)*128+u];
        float w0 = W_in[u], w1 = W_in[128+u];
        s0 = fmaf(sh_pos[a0  ][0], w0, fmaf(sh_pos[a0  ][1], w1, s0));
        s1 = fmaf(sh_pos[a0+2][0], w0, fmaf(sh_pos[a0+2][1], w1, s1));
        float w8[8];
        #pragma unroll
        for (int kb=0;kb<8;kb++){
            #pragma unroll
            for (int r=0;r<8;r++) w8[r] = W_in[(98+kb*8+r)*128+u];
            #pragma unroll
            for (int r=0;r<8;r++){
                s0 = fmaf(sh_ctx[a0  ][kb*8+r], w8[r], s0);
                s1 = fmaf(sh_ctx[a0+2][kb*8+r], w8[r], s1);
            }
        }
        sh_xT[u*4 + a0    ] = fmaxf(s0,0.f);
        sh_xT[u*4 + a0 + 2] = fmaxf(s1,0.f);
    }
    __syncthreads();

    // ---- gates = x@W_ih^T + h@W_hh^T + b ; transposed global weights, f32x2 --------
    // buf layout: agent-major, buf[a*256 + u] where u = gate*64 + dim
    {
        float binit = b_ih[tid] + b_hh[tid];
        ull acc01 = f32x2_dup(binit);
        ull acc23 = acc01;
        float w8[8];
        #pragma unroll
        for (int vb=0; vb<16; vb++){
            #pragma unroll
            for (int r=0;r<8;r++) w8[r] = g_WihT[(vb*8+r)*256+tid];
            #pragma unroll
            for (int r=0;r<8;r++){
                ulonglong2 xv = *(const ulonglong2*)(sh_xT + (vb*8+r)*4);
                ull wd = f32x2_dup(w8[r]);
                acc01 = f32x2_fma(xv.x, wd, acc01);
                acc23 = f32x2_fma(xv.y, wd, acc23);
            }
        }
        #pragma unroll
        for (int vb=0; vb<8; vb++){
            #pragma unroll
            for (int r=0;r<8;r++) w8[r] = g_WhhT[(vb*8+r)*256+tid];
            #pragma unroll
            for (int r=0;r<8;r++){
                ulonglong2 hv = *(const ulonglong2*)(sh_hT + (vb*8+r)*4);
                ull wd = f32x2_dup(w8[r]);
                acc01 = f32x2_fma(hv.x, wd, acc01);
                acc23 = f32x2_fma(hv.y, wd, acc23);
            }
        }
        float a0,a1,a2,a3;
        UNPACK2(a0,a1,acc01);
        UNPACK2(a2,a3,acc23);
        buf[0*256+tid]=a0; buf[1*256+tid]=a1; buf[2*256+tid]=a2; buf[3*256+tid]=a3;
    }
    __syncthreads();

    // ---- LSTM elementwise (256 threads = 4 agents x 64 dims) ----
    // buf is agent-major: buf[a*256 + gate*64 + d]
    {
        int a = tid>>6, d = tid&63; int i = abase+a;
        float ig = buf[a*256 +   0 + d];
        float fg = buf[a*256 +  64 + d];
        float gg = buf[a*256 + 128 + d];
        float og = buf[a*256 + 192 + d];
        float co = g_c[i*64+d];
        float cn = sigmf(fg)*co + sigmf(ig)*tanhf(gg);
        float hn = sigmf(og)*tanhf(cn);
        g_c[i*64+d] = cn;
        g_h[i*64+d] = hn;
        sh_hnew[a][d] = hn;
    }
    __syncthreads();

    // ---- A'[j]=h@W1[32:96] - cur_j.M,  B'[i]=h@W1[96:160]+bc + cur_i.M -------------
    {
        int m = tid & 63; int w = (tid>>6)&1; int ah = tid>>7;  // agents ah, ah+2
        float s0 = w ? g_bc[m] : 0.f; float s1 = s0;
        const float* Wp = W1 + (32 + w*64)*64 + m;
        float w8[8];
        #pragma unroll
        for (int db=0; db<8; db++){
            #pragma unroll
            for (int r=0;r<8;r++) w8[r] = Wp[(db*8+r)*64];
            #pragma unroll
            for (int r=0;r<8;r++){
                s0 = fmaf(sh_hnew[ah  ][db*8+r], w8[r], s0);
                s1 = fmaf(sh_hnew[ah+2][db*8+r], w8[r], s1);
            }
        }
        float m0 = g_M[m], m1 = g_M[64+m];
        float sg = w ? 1.f : -1.f;
        float cx0 = g_cur[(abase+ah  )*2], cy0 = g_cur[(abase+ah  )*2+1];
        float cx1 = g_cur[(abase+ah+2)*2], cy1 = g_cur[(abase+ah+2)*2+1];
        s0 = fmaf(sg*cx0, m0, fmaf(sg*cy0, m1, s0));
        s1 = fmaf(sg*cx1, m0, fmaf(sg*cy1, m1, s1));
        float* dst = w ? g_B : g_A;
        dst[(abase+ah  )*64+m] = s0;
        dst[(abase+ah+2)*64+m] = s1;
    }
}

// ---------------- pooling kernel: 512 blocks (1 row i), 256 threads, 128-pair tiles -
// stage 1: h1[m][p] = relu(A'[j_p][m] + B'[i][m]); stage 2: f32x2 GEMM + masked max.
// W2 read directly from global (L1-resident, 16KB) — no smem staging.
__global__ __launch_bounds__(256, 3)
void k_pool(int t, const int* __restrict__ nei,
            const float* __restrict__ W2, const float* __restrict__ b2)
{
    __shared__ __align__(16) float sh_h1[64*132];  // [m][p] stride 132; red aliased
    __shared__ int   sh_jidx[NP];
    __shared__ int   sh_cnt;

    const int tid = threadIdx.x;
    const int i = blockIdx.x;
    const float4* W2v = (const float4*)W2;         // [m][kq] quads

    if (tid == 0) sh_cnt = 0;
    __syncthreads();

    // ---- compact valid neighbor indices (max is commutative; order irrelevant) ----
    {
        const int* row = nei + (long)t*NP*NP + (long)i*NP;
        #pragma unroll
        for (int c=0;c<2;c++){
            int j = c*256 + tid;
            int v = row[j] > 0;
            unsigned bal = __ballot_sync(0xFFFFFFFFu, v);
            int lane = tid & 31;
            int base = 0;
            if (lane == 0) base = atomicAdd(&sh_cnt, __popc(bal));
            base = __shfl_sync(0xFFFFFFFFu, base, 0);
            if (v) sh_jidx[base + __popc(bal & ((1u<<lane)-1u))] = j;
        }
    }
    __syncthreads();
    const int cnt = sh_cnt;
    const int ntiles = (cnt + 127) >> 7;

    const int mm = tid & 63, q = tid >> 6;      // stage-1 mapping
    const float Bi = g_B[i*64+mm];

    const int kq = tid & 15, jg = tid >> 4;     // 16 j-groups of 8, 16 k-quads
    float b2r[4];
    #pragma unroll
    for (int kk=0;kk<4;kk++) b2r[kk] = b2[kq*4+kk];
    float cacc[4] = {0.f,0.f,0.f,0.f};

    for (int jt=0; jt<ntiles; jt++){
        const int tile_cnt = min(128, cnt - jt*128);
        __syncthreads();                         // protect sh_h1 reuse

        // stage 1: h1 for valid pairs x 64 m; batched loads, skip invalid 32-chunks
        #pragma unroll
        for (int rb=0; rb<4; rb++){
            if (rb*32 < tile_cnt){
                float a8[8];
                #pragma unroll
                for (int r2=0; r2<8; r2++){
                    int p = (rb*8+r2)*4 + q;
                    int gp = jt*128 + p;
                    int j = sh_jidx[(gp < cnt) ? gp : 0];
                    a8[r2] = g_A[j*64 + mm];
                }
                #pragma unroll
                for (int r2=0; r2<8; r2++){
                    int p = (rb*8+r2)*4 + q;
                    sh_h1[mm*132 + p] = fmaxf(a8[r2] + Bi, 0.f);
                }
            }
        }
        __syncthreads();

        // stage 2: packed f32x2 GEMM, 4 j-pairs x 4 k per thread; skip idle warps
        if (jg*8 < tile_cnt){
            ull acc2[4][4];
            #pragma unroll
            for (int jp=0;jp<4;jp++)
                #pragma unroll
                for (int kk=0;kk<4;kk++) acc2[jp][kk] = 0ull;

            #pragma unroll 8
            for (int m=0;m<64;m++){
                const float4 wv = __ldg(W2v + m*16 + kq);
                ull w0 = f32x2_dup(wv.x), w1 = f32x2_dup(wv.y);
                ull w2 = f32x2_dup(wv.z), w3 = f32x2_dup(wv.w);
                const ull* hp = (const ull*)(sh_h1 + m*132 + (jg<<3));
                ulonglong2 hA = *(const ulonglong2*)(hp);
                ulonglong2 hB = *(const ulonglong2*)(hp+2);
                acc2[0][0]=f32x2_fma(hA.x,w0,acc2[0][0]);
                acc2[0][1]=f32x2_fma(hA.x,w1,acc2[0][1]);
                acc2[0][2]=f32x2_fma(hA.x,w2,acc2[0][2]);
                acc2[0][3]=f32x2_fma(hA.x,w3,acc2[0][3]);
                acc2[1][0]=f32x2_fma(hA.y,w0,acc2[1][0]);
                acc2[1][1]=f32x2_fma(hA.y,w1,acc2[1][1]);
                acc2[1][2]=f32x2_fma(hA.y,w2,acc2[1][2]);
                acc2[1][3]=f32x2_fma(hA.y,w3,acc2[1][3]);
                acc2[2][0]=f32x2_fma(hB.x,w0,acc2[2][0]);
                acc2[2][1]=f32x2_fma(hB.x,w1,acc2[2][1]);
                acc2[2][2]=f32x2_fma(hB.x,w2,acc2[2][2]);
                acc2[2][3]=f32x2_fma(hB.x,w3,acc2[2][3]);
                acc2[3][0]=f32x2_fma(hB.y,w0,acc2[3][0]);
                acc2[3][1]=f32x2_fma(hB.y,w1,acc2[3][1]);
                acc2[3][2]=f32x2_fma(hB.y,w2,acc2[3][2]);
                acc2[3][3]=f32x2_fma(hB.y,w3,acc2[3][3]);
            }

            #pragma unroll
            for (int jp=0;jp<4;jp++){
                int gp0 = jt*128 + jg*8 + jp*2;
                #pragma unroll
                for (int kk=0;kk<4;kk++){
                    float lo, hi;
                    UNPACK2(lo, hi, acc2[jp][kk]);
                    if (gp0     < cnt) cacc[kk] = fmaxf(cacc[kk], lo + b2r[kk]);
                    if (gp0 + 1 < cnt) cacc[kk] = fmaxf(cacc[kk], hi + b2r[kk]);
                }
            }
        }
    }

    // final reduction over 16 jg groups; alias reduction buffer onto sh_h1
    __syncthreads();
    float* sh_red = sh_h1;
    #pragma unroll
    for (int kk=0;kk<4;kk++) sh_red[jg*64 + kq*4+kk] = cacc[kk];
    __syncthreads();
    if (tid < 64){
        float v = sh_red[tid];
        #pragma unroll
        for (int g=1; g<16; g++) v = fmaxf(v, sh_red[g*64 + tid]);
        g_ctx[i*64 + tid] = v;
    }
}

// ---------------- launch ------------------------------------------------------------
extern "C" void kernel_launch(void* const* d_in, const int* in_sizes, int n_in,
                              void* d_out, int out_size)
{
    const float* last_pos = (const float*)d_in[0];
    const float* c_in     = (const float*)d_in[1];
    const float* z        = (const float*)d_in[2];
    const float* obs      = (const float*)d_in[3];
    const int*   nei      = (const int*)  d_in[4];
    // d_in[5] nei_num_index: unused by reference
    const float* h0       = (const float*)d_in[6];
    const float* c0       = (const float*)d_in[7];
    const float* eps      = (const float*)d_in[8];
    const float* W_in     = (const float*)d_in[9];
    const float* b_in     = (const float*)d_in[10];
    const float* W_ih     = (const float*)d_in[11];
    const float* W_hh     = (const float*)d_in[12];
    const float* b_ih     = (const float*)d_in[13];
    const float* b_hh     = (const float*)d_in[14];
    const float* W_l2p    = (const float*)d_in[15];
    const float* b_l2p    = (const float*)d_in[16];
    const float* W_sp     = (const float*)d_in[17];
    const float* b_sp     = (const float*)d_in[18];
    const float* W1       = (const float*)d_in[19];
    const float* b1       = (const float*)d_in[20];
    const float* W2       = (const float*)d_in[21];
    const float* b2       = (const float*)d_in[22];
    float* out = (float*)d_out;

    k_init<<<128, 256>>>(last_pos, obs, h0, c0, W_sp, b_sp, W1, b1, W_ih, W_hh);
    k_xc<<<128, 128>>>(c_in, z, W_in, b_in);

    for (int t=0; t<TT; t++){
        k_agent<<<128, 256>>>(t, eps, W_in, b_ih, b_hh, W_l2p, b_l2p, W1, out);
        k_pool<<<512, 256>>>(t, nei, W2, b2);
    }
    // final post (outputs for t = 11)
    k_agent<<<128, 256>>>(TT, eps, W_in, b_ih, b_hh, W_l2p, b_l2p, W1, out);
}